// round 4
// baseline (speedup 1.0000x reference)
#include <cuda_runtime.h>

#define N_NODES 100000
#define N_EDGES 1000000
#define IN_DIM  128
#define HID     64
#define NG      2048

// ---------------- scratch (static __device__, no allocation) ----------------
__device__ int   g_eor, g_bor;        // detection OR-accumulators
__device__ int   g_ei64, g_b64;       // 1 if that input is int64
__device__ int   g_deg[N_NODES];
__device__ float g_dinv[N_NODES];
__device__ int   g_col[N_EDGES];
__device__ int   g_off[N_NODES];
__device__ int   g_cur[N_NODES];
__device__ int   g_csr[N_EDGES];
__device__ int   g_alloc;
__device__ __align__(16) float g_bufA[N_NODES * HID];   // GEMM output
__device__ __align__(16) float g_bufB[N_NODES * HID];   // aggregated+relu output
__device__ __align__(16) float g_pooled[NG * HID];

__device__ __forceinline__ int clampi(int v, int lo, int hi) {
    return v < lo ? lo : (v > hi ? hi : v);
}

// ---------------- pre: zero detection accumulators + alloc counter ----------------
__global__ void k_pre() {
    g_eor = 0; g_bor = 0; g_alloc = 0;
}

// ------- init: deg=1 (self loop), pooled=0; also dtype detection ORs -------
// ew/bw are the int32 word views of edge_index and batch.
__global__ void k_init(const int* __restrict__ ew, const int* __restrict__ bw) {
    int i = blockIdx.x * blockDim.x + threadIdx.x;
    if (i < N_NODES) g_deg[i] = 1;
    if (i < NG * HID) g_pooled[i] = 0.f;
    // detection: OR odd 32-bit words. If data is int64 (values < 2^31), these
    // are the high halves == 0. If data is int32, they are real values.
    if (i < 1024) {
        int w = ew[2 * i + 1];               // word idx <= 2047 < 2M, safe either way
        if (w != 0) atomicOr(&g_eor, 1);
        int b = bw[2 * i + 1];               // word idx <= 2047 < 100000, safe
        if (b != 0) atomicOr(&g_bor, 1);
    }
}

__global__ void k_flag() {
    g_ei64 = (g_eor == 0) ? 1 : 0;
    g_b64  = (g_bor == 0) ? 1 : 0;
}

// ---------------- edge pass: count in-degree (dst = edge_index[1]) ----------------
__global__ void k_edges(const int* __restrict__ ew) {
    int e = blockIdx.x * blockDim.x + threadIdx.x;
    if (e >= N_EDGES) return;
    int idx = N_EDGES + e;
    int c = g_ei64 ? ew[2 * idx] : ew[idx];   // little-endian low word
    c = clampi(c, 0, N_NODES - 1);
    g_col[e] = c;
    atomicAdd(&g_deg[c], 1);
}

// ------- per node: dinv, and atomic range allocation (no prefix scan) -------
__global__ void k_alloc() {
    int i = blockIdx.x * blockDim.x + threadIdx.x;
    if (i >= N_NODES) return;
    int d = g_deg[i];
    g_dinv[i] = rsqrtf((float)d);
    int o = atomicAdd(&g_alloc, d - 1);       // edges excluding self loop
    g_off[i] = o;
    g_cur[i] = o;
}

// ---------------- fill CSR: slot via per-node cursor ----------------
__global__ void k_fill(const int* __restrict__ ew) {
    int e = blockIdx.x * blockDim.x + threadIdx.x;
    if (e >= N_EDGES) return;
    int r = g_ei64 ? ew[2 * e] : ew[e];
    r = clampi(r, 0, N_NODES - 1);
    int c = g_col[e];
    int s = atomicAdd(&g_cur[c], 1);
    if (s >= 0 && s < N_EDGES) g_csr[s] = r;
}

// ---------------- GEMM body: g_bufA[N,64] = X[N,KD] @ W[KD,64] ----------------
// block = 256 threads; tile 64 rows x 64 cols; thread tile 4x4; K staged in 64-chunks.
template <int KD>
__device__ __forceinline__ void gemm_body(const float* X, const float* __restrict__ W) {
    __shared__ float xs[64 * 64];
    __shared__ float ws[64 * 64];

    int tid = threadIdx.x;
    int tr = tid >> 4;
    int tc = tid & 15;
    int row0 = blockIdx.x * 64;

    float acc[4][4];
#pragma unroll
    for (int i = 0; i < 4; i++)
#pragma unroll
        for (int j = 0; j < 4; j++) acc[i][j] = 0.f;

    for (int ko = 0; ko < KD; ko += 64) {
        for (int idx = tid; idx < 64 * 64; idx += 256) {
            int r = idx >> 6;
            int c = idx & 63;
            int gr = row0 + r;
            float v = 0.f;
            if (gr < N_NODES) v = X[gr * KD + ko + c];
            xs[r * 64 + c] = v;
        }
        for (int idx = tid; idx < 64 * 64; idx += 256) {
            int r = idx >> 6;
            int c = idx & 63;
            ws[r * 64 + c] = W[(ko + r) * 64 + c];
        }
        __syncthreads();

#pragma unroll 4
        for (int k = 0; k < 64; k++) {
            float a0 = xs[(tr * 4 + 0) * 64 + k];
            float a1 = xs[(tr * 4 + 1) * 64 + k];
            float a2 = xs[(tr * 4 + 2) * 64 + k];
            float a3 = xs[(tr * 4 + 3) * 64 + k];
            float w0 = ws[k * 64 + tc * 4 + 0];
            float w1 = ws[k * 64 + tc * 4 + 1];
            float w2 = ws[k * 64 + tc * 4 + 2];
            float w3 = ws[k * 64 + tc * 4 + 3];
            acc[0][0] = fmaf(a0, w0, acc[0][0]); acc[0][1] = fmaf(a0, w1, acc[0][1]);
            acc[0][2] = fmaf(a0, w2, acc[0][2]); acc[0][3] = fmaf(a0, w3, acc[0][3]);
            acc[1][0] = fmaf(a1, w0, acc[1][0]); acc[1][1] = fmaf(a1, w1, acc[1][1]);
            acc[1][2] = fmaf(a1, w2, acc[1][2]); acc[1][3] = fmaf(a1, w3, acc[1][3]);
            acc[2][0] = fmaf(a2, w0, acc[2][0]); acc[2][1] = fmaf(a2, w1, acc[2][1]);
            acc[2][2] = fmaf(a2, w2, acc[2][2]); acc[2][3] = fmaf(a2, w3, acc[2][3]);
            acc[3][0] = fmaf(a3, w0, acc[3][0]); acc[3][1] = fmaf(a3, w1, acc[3][1]);
            acc[3][2] = fmaf(a3, w2, acc[3][2]); acc[3][3] = fmaf(a3, w3, acc[3][3]);
        }
        __syncthreads();
    }

#pragma unroll
    for (int i = 0; i < 4; i++) {
        int gr = row0 + tr * 4 + i;
        if (gr < N_NODES) {
#pragma unroll
            for (int j = 0; j < 4; j++)
                g_bufA[gr * 64 + tc * 4 + j] = acc[i][j];
        }
    }
}

__global__ __launch_bounds__(256) void k_gemm1(const float* __restrict__ X,
                                               const float* __restrict__ W) {
    gemm_body<IN_DIM>(X, W);
}

__global__ __launch_bounds__(256) void k_gemm2(const float* __restrict__ W) {
    gemm_body<HID>(g_bufB, W);
}

// -------- pull-aggregate: out = relu(dinv[i] * sum(dinv[src]*h[src]) + b) --------
__global__ __launch_bounds__(256) void k_agg(const float* __restrict__ bias) {
    int warp = (blockIdx.x * blockDim.x + threadIdx.x) >> 5;
    int lane = threadIdx.x & 31;
    if (warp >= N_NODES) return;
    int i = warp;

    float di = g_dinv[i];
    float2 hs = *reinterpret_cast<const float2*>(g_bufA + i * 64 + 2 * lane);
    float ax = di * hs.x;
    float ay = di * hs.y;

    int beg = g_off[i];
    int end = beg + g_deg[i] - 1;
    if (beg < 0) beg = 0;
    if (end > N_EDGES) end = N_EDGES;
    int e = beg;
    for (; e + 4 <= end; e += 4) {
        int s0 = g_csr[e], s1 = g_csr[e + 1], s2 = g_csr[e + 2], s3 = g_csr[e + 3];
        float w0 = g_dinv[s0], w1 = g_dinv[s1], w2 = g_dinv[s2], w3 = g_dinv[s3];
        float2 v0 = *reinterpret_cast<const float2*>(g_bufA + s0 * 64 + 2 * lane);
        float2 v1 = *reinterpret_cast<const float2*>(g_bufA + s1 * 64 + 2 * lane);
        float2 v2 = *reinterpret_cast<const float2*>(g_bufA + s2 * 64 + 2 * lane);
        float2 v3 = *reinterpret_cast<const float2*>(g_bufA + s3 * 64 + 2 * lane);
        ax += w0 * v0.x + w1 * v1.x + w2 * v2.x + w3 * v3.x;
        ay += w0 * v0.y + w1 * v1.y + w2 * v2.y + w3 * v3.y;
    }
    for (; e < end; e++) {
        int s = g_csr[e];
        float w = g_dinv[s];
        float2 v = *reinterpret_cast<const float2*>(g_bufA + s * 64 + 2 * lane);
        ax += w * v.x;
        ay += w * v.y;
    }

    float bx = bias[2 * lane];
    float by = bias[2 * lane + 1];
    float2 o;
    o.x = fmaxf(di * ax + bx, 0.f);
    o.y = fmaxf(di * ay + by, 0.f);
    *reinterpret_cast<float2*>(g_bufB + i * 64 + 2 * lane) = o;
}

// -------- fused score + segmented pooling (batch is sorted) --------
__global__ __launch_bounds__(256) void k_pool(const int* __restrict__ bw,
                                              const float* __restrict__ aw,
                                              const float* __restrict__ ab,
                                              const float* __restrict__ mw,
                                              const float* __restrict__ mb) {
    int warp = (blockIdx.x * blockDim.x + threadIdx.x) >> 5;
    int lane = threadIdx.x & 31;
    int n0 = warp * 32;
    if (n0 >= N_NODES) return;
    int n1 = n0 + 32;
    if (n1 > N_NODES) n1 = N_NODES;

    int b64 = g_b64;
    float awx = aw[2 * lane], awy = aw[2 * lane + 1];
    float mwx = mw[2 * lane], mwy = mw[2 * lane + 1];
    float abv = ab[0], mbv = mb[0];

    int cur = -1;
    float accx = 0.f, accy = 0.f;
    for (int n = n0; n < n1; n++) {
        float2 h = *reinterpret_cast<const float2*>(g_bufB + n * 64 + 2 * lane);
        float pa = h.x * awx + h.y * awy;
        float pm = h.x * mwx + h.y * mwy;
#pragma unroll
        for (int o = 16; o > 0; o >>= 1) {
            pa += __shfl_xor_sync(0xffffffffu, pa, o);
            pm += __shfl_xor_sync(0xffffffffu, pm, o);
        }
        float score = (pa + abv) * (1.f / (1.f + expf(-(pm + mbv))));
        int g = b64 ? bw[2 * n] : bw[n];
        g = clampi(g, 0, NG - 1);
        if (g != cur) {
            if (cur >= 0) {
                atomicAdd(&g_pooled[cur * 64 + 2 * lane], accx);
                atomicAdd(&g_pooled[cur * 64 + 2 * lane + 1], accy);
            }
            cur = g;
            accx = 0.f;
            accy = 0.f;
        }
        accx += score * h.x;
        accy += score * h.y;
    }
    if (cur >= 0) {
        atomicAdd(&g_pooled[cur * 64 + 2 * lane], accx);
        atomicAdd(&g_pooled[cur * 64 + 2 * lane + 1], accy);
    }
}

// -------- final: out[g] = pooled[g] . out_w + out_b --------
__global__ void k_final(const float* __restrict__ ow, const float* __restrict__ ob,
                        float* __restrict__ out) {
    int warp = (blockIdx.x * blockDim.x + threadIdx.x) >> 5;
    int lane = threadIdx.x & 31;
    if (warp >= NG) return;
    float2 p = *reinterpret_cast<const float2*>(g_pooled + warp * 64 + 2 * lane);
    float wx = ow[2 * lane], wy = ow[2 * lane + 1];
    float s = p.x * wx + p.y * wy;
#pragma unroll
    for (int o = 16; o > 0; o >>= 1) s += __shfl_xor_sync(0xffffffffu, s, o);
    if (lane == 0) out[warp] = s + ob[0];
}

// ---------------------------------------------------------------------------
extern "C" void kernel_launch(void* const* d_in, const int* in_sizes, int n_in,
                              void* d_out, int out_size) {
    const float* x     = (const float*)d_in[0];
    const int*   ew    = (const int*)d_in[1];    // int32 word view of edge_index
    const int*   bw    = (const int*)d_in[2];    // int32 word view of batch
    const float* W1    = (const float*)d_in[3];
    const float* b1    = (const float*)d_in[4];
    const float* W2    = (const float*)d_in[5];
    const float* b2    = (const float*)d_in[6];
    const float* aw    = (const float*)d_in[7];
    const float* ab    = (const float*)d_in[8];
    const float* mw    = (const float*)d_in[9];
    const float* mb    = (const float*)d_in[10];
    const float* ow    = (const float*)d_in[11];
    const float* ob    = (const float*)d_in[12];
    float* out = (float*)d_out;

    k_pre<<<1, 1>>>();
    k_init<<<(NG * HID + 255) / 256, 256>>>(ew, bw);
    k_flag<<<1, 1>>>();
    k_edges<<<(N_EDGES + 255) / 256, 256>>>(ew);
    k_alloc<<<(N_NODES + 255) / 256, 256>>>();
    k_fill<<<(N_EDGES + 255) / 256, 256>>>(ew);

    int gemm_grid = (N_NODES + 63) / 64;
    k_gemm1<<<gemm_grid, 256>>>(x, W1);
    k_agg<<<(N_NODES * 32 + 255) / 256, 256>>>(b1);
    k_gemm2<<<gemm_grid, 256>>>(W2);
    k_agg<<<(N_NODES * 32 + 255) / 256, 256>>>(b2);
    k_pool<<<(N_NODES + 255) / 256, 256>>>(bw, aw, ab, mw, mb);
    k_final<<<(NG * 32 + 255) / 256, 256>>>(ow, ob, out);
}

// round 5
// speedup vs baseline: 1.1093x; 1.1093x over previous
#include <cuda_runtime.h>

#define N_NODES 100000
#define N_EDGES 1000000
#define IN_DIM  128
#define HID     64
#define NG      2048

// ---------------- scratch (static __device__, no allocation) ----------------
__device__ int   g_eor, g_bor;        // detection OR-accumulators
__device__ int   g_ei64, g_b64;       // 1 if that input is int64
__device__ int   g_deg[N_NODES];
__device__ float g_dinv[N_NODES];
__device__ int   g_col[N_EDGES];
__device__ int   g_off[N_NODES];
__device__ int   g_cur[N_NODES];
__device__ int   g_csr[N_EDGES];
__device__ int   g_alloc;
__device__ __align__(16) float g_bufA[N_NODES * HID];   // dinv-scaled GEMM output
__device__ __align__(16) float g_bufB[N_NODES * HID];   // aggregated+relu output
__device__ __align__(16) float g_pooled[NG * HID];

__device__ __forceinline__ int clampi(int v, int lo, int hi) {
    return v < lo ? lo : (v > hi ? hi : v);
}

// ---------------- tf32 helpers ----------------
__device__ __forceinline__ unsigned f2tf(float x) {
    unsigned r;
    asm("cvt.rna.tf32.f32 %0, %1;" : "=r"(r) : "f"(x));
    return r;
}

__device__ __forceinline__ void mma_tf32(float* d, const unsigned* a, const unsigned* b) {
    asm volatile(
        "mma.sync.aligned.m16n8k8.row.col.f32.tf32.tf32.f32 "
        "{%0,%1,%2,%3},{%4,%5,%6,%7},{%8,%9},{%0,%1,%2,%3};\n"
        : "+f"(d[0]), "+f"(d[1]), "+f"(d[2]), "+f"(d[3])
        : "r"(a[0]), "r"(a[1]), "r"(a[2]), "r"(a[3]), "r"(b[0]), "r"(b[1]));
}

// ---------------- pre: zero detection accumulators + alloc counter ----------------
__global__ void k_pre() {
    g_eor = 0; g_bor = 0; g_alloc = 0;
}

// ------- init: deg=1 (self loop), pooled=0; also dtype detection ORs -------
__global__ void k_init(const int* __restrict__ ew, const int* __restrict__ bw) {
    int i = blockIdx.x * blockDim.x + threadIdx.x;
    if (i < N_NODES) g_deg[i] = 1;
    if (i < NG * HID) g_pooled[i] = 0.f;
    if (i < 1024) {
        if (ew[2 * i + 1] != 0) atomicOr(&g_eor, 1);
        if (bw[2 * i + 1] != 0) atomicOr(&g_bor, 1);
    }
}

__global__ void k_flag() {
    g_ei64 = (g_eor == 0) ? 1 : 0;
    g_b64  = (g_bor == 0) ? 1 : 0;
}

// ---------------- edge pass: count in-degree (dst = edge_index[1]) ----------------
__global__ void k_edges(const int* __restrict__ ew) {
    int e = blockIdx.x * blockDim.x + threadIdx.x;
    if (e >= N_EDGES) return;
    int idx = N_EDGES + e;
    int c;
    if (g_ei64) c = reinterpret_cast<const int2*>(ew)[idx].x;
    else        c = ew[idx];
    c = clampi(c, 0, N_NODES - 1);
    g_col[e] = c;
    atomicAdd(&g_deg[c], 1);
}

// ------- per node: dinv, atomic range allocation (no prefix scan) -------
__global__ void k_alloc() {
    int i = blockIdx.x * blockDim.x + threadIdx.x;
    if (i >= N_NODES) return;
    int d = g_deg[i];
    g_dinv[i] = rsqrtf((float)d);
    int o = atomicAdd(&g_alloc, d - 1);
    g_off[i] = o;
    g_cur[i] = o;
}

// ---------------- fill CSR: slot via per-node cursor ----------------
__global__ void k_fill(const int* __restrict__ ew) {
    int e = blockIdx.x * blockDim.x + threadIdx.x;
    if (e >= N_EDGES) return;
    int r;
    if (g_ei64) r = reinterpret_cast<const int2*>(ew)[e].x;
    else        r = ew[e];
    r = clampi(r, 0, N_NODES - 1);
    int c = g_col[e];
    int s = atomicAdd(&g_cur[c], 1);
    if (s >= 0 && s < N_EDGES) g_csr[s] = r;
}

// ---------------- 3xTF32 MMA GEMM: g_bufA[r][:] = dinv[r] * (X[r][:] @ W) ----------------
// Block: 128 threads (4 warps). Block tile 128 rows x 64 cols. Warp: 32 rows x 64 cols
// = 2 m16 x 8 n8 atoms of m16n8k8. K staged in 32-chunks, operands pre-swizzled
// into fragment order in smem.
template <int KD>
__device__ __forceinline__ void gemm_mma_body(const float* X, const float* __restrict__ W) {
    // abuf: [k8(4)][m16(8)][lane(32)][reg(4)]  = 4096 floats (16KB)
    // bbuf: [k8(4)][na(8)][lane(32)][reg(2)]   = 2048 floats (8KB)
    __shared__ float abuf[4096];
    __shared__ float bbuf[2048];

    int tid  = threadIdx.x;
    int lane = tid & 31;
    int warp = tid >> 5;
    int row0 = blockIdx.x * 128;

    float acc[2][8][4];
#pragma unroll
    for (int m = 0; m < 2; m++)
#pragma unroll
        for (int na = 0; na < 8; na++)
#pragma unroll
            for (int q = 0; q < 4; q++) acc[m][na][q] = 0.f;

    for (int ko = 0; ko < KD; ko += 32) {
        __syncthreads();
        // ---- stage A chunk: 128 rows x 32 k, scatter into fragment order ----
#pragma unroll
        for (int it = 0; it < 8; it++) {
            int f4 = it * 128 + tid;            // 0..1023
            int r  = f4 >> 3;                   // 0..127
            int c4 = (f4 & 7) * 4;              // 0..28
            int gr = row0 + r;
            float4 v = make_float4(0.f, 0.f, 0.f, 0.f);
            if (gr < N_NODES)
                v = *reinterpret_cast<const float4*>(X + gr * KD + ko + c4);
            int rr  = r & 15;
            int m16 = r >> 4;
            int k8  = c4 >> 3;                  // 0..3
            int kkb = c4 & 7;                   // 0 or 4
            float vv[4] = {v.x, v.y, v.z, v.w};
#pragma unroll
            for (int j = 0; j < 4; j++) {
                int kk  = kkb + j;
                int reg = ((rr >= 8) ? 1 : 0) + ((kk >= 4) ? 2 : 0);
                int t   = (rr & 7) * 4 + (kk & 3);
                abuf[((k8 * 8 + m16) * 32 + t) * 4 + reg] = vv[j];
            }
        }
        // ---- stage B chunk: 32 k x 64 n ----
#pragma unroll
        for (int it = 0; it < 4; it++) {
            int f4 = it * 128 + tid;            // 0..511
            int r  = f4 >> 4;                   // k: 0..31
            int c4 = (f4 & 15) * 4;             // n: 0..60
            float4 w = *reinterpret_cast<const float4*>(W + (ko + r) * 64 + c4);
            int kk = r & 7;
            int k8 = r >> 3;
            float wv[4] = {w.x, w.y, w.z, w.w};
#pragma unroll
            for (int j = 0; j < 4; j++) {
                int n   = c4 + j;
                int na  = n >> 3;
                int nn  = n & 7;
                int reg = (kk >= 4) ? 1 : 0;
                int t   = nn * 4 + (kk & 3);
                bbuf[((k8 * 8 + na) * 32 + t) * 2 + reg] = wv[j];
            }
        }
        __syncthreads();

        // ---- 4 k8-steps of MMA ----
#pragma unroll
        for (int k8 = 0; k8 < 4; k8++) {
            // A fragments (2 m-atoms), split hi/lo
            unsigned a_hi[2][4], a_lo[2][4];
#pragma unroll
            for (int m = 0; m < 2; m++) {
                float4 ar = *reinterpret_cast<const float4*>(
                    abuf + ((k8 * 8 + warp * 2 + m) * 32 + lane) * 4);
                float av[4] = {ar.x, ar.y, ar.z, ar.w};
#pragma unroll
                for (int q = 0; q < 4; q++) {
                    unsigned h = f2tf(av[q]);
                    a_hi[m][q] = h;
                    a_lo[m][q] = f2tf(av[q] - __uint_as_float(h));
                }
            }
            // B fragments (8 n-atoms), split hi/lo
            unsigned b_hi[8][2], b_lo[8][2];
#pragma unroll
            for (int na = 0; na < 8; na++) {
                float2 br = *reinterpret_cast<const float2*>(
                    bbuf + ((k8 * 8 + na) * 32 + lane) * 2);
                float bv[2] = {br.x, br.y};
#pragma unroll
                for (int q = 0; q < 2; q++) {
                    unsigned h = f2tf(bv[q]);
                    b_hi[na][q] = h;
                    b_lo[na][q] = f2tf(bv[q] - __uint_as_float(h));
                }
            }
            // 3xTF32: ah*bh + ah*bl + al*bh
#pragma unroll
            for (int na = 0; na < 8; na++) {
#pragma unroll
                for (int m = 0; m < 2; m++) {
                    mma_tf32(acc[m][na], a_hi[m], b_hi[na]);
                    mma_tf32(acc[m][na], a_hi[m], b_lo[na]);
                    mma_tf32(acc[m][na], a_lo[m], b_hi[na]);
                }
            }
        }
    }

    // ---- epilogue: u = dinv[row] * acc -> g_bufA ----
    int rbase = row0 + warp * 32 + (lane >> 2);
    int cbase = (lane & 3) * 2;
#pragma unroll
    for (int m = 0; m < 2; m++) {
        int r_lo = rbase + m * 16;
        int r_hi = r_lo + 8;
        float d_lo = (r_lo < N_NODES) ? g_dinv[r_lo] : 0.f;
        float d_hi = (r_hi < N_NODES) ? g_dinv[r_hi] : 0.f;
#pragma unroll
        for (int na = 0; na < 8; na++) {
            int c = na * 8 + cbase;
            if (r_lo < N_NODES) {
                float2 v; v.x = d_lo * acc[m][na][0]; v.y = d_lo * acc[m][na][1];
                *reinterpret_cast<float2*>(g_bufA + r_lo * 64 + c) = v;
            }
            if (r_hi < N_NODES) {
                float2 v; v.x = d_hi * acc[m][na][2]; v.y = d_hi * acc[m][na][3];
                *reinterpret_cast<float2*>(g_bufA + r_hi * 64 + c) = v;
            }
        }
    }
}

__global__ __launch_bounds__(128) void k_gemm1(const float* __restrict__ X,
                                               const float* __restrict__ W) {
    gemm_mma_body<IN_DIM>(X, W);
}

__global__ __launch_bounds__(128) void k_gemm2(const float* __restrict__ W) {
    gemm_mma_body<HID>(g_bufB, W);
}

// -------- pull-aggregate: out = relu(dinv[i] * (u_i + sum u_src) + b) --------
// bufA already holds u = dinv*h. One warp per node, float2 per lane.
__global__ __launch_bounds__(256) void k_agg(const float* __restrict__ bias) {
    int warp = (blockIdx.x * blockDim.x + threadIdx.x) >> 5;
    int lane = threadIdx.x & 31;
    if (warp >= N_NODES) return;
    int i = warp;

    float2 hs = *reinterpret_cast<const float2*>(g_bufA + i * 64 + 2 * lane);
    float ax = hs.x;
    float ay = hs.y;

    int beg = g_off[i];
    int end = beg + g_deg[i] - 1;
    if (beg < 0) beg = 0;
    if (end > N_EDGES) end = N_EDGES;
    int e = beg;
    for (; e + 4 <= end; e += 4) {
        int s0 = g_csr[e], s1 = g_csr[e + 1], s2 = g_csr[e + 2], s3 = g_csr[e + 3];
        float2 v0 = *reinterpret_cast<const float2*>(g_bufA + s0 * 64 + 2 * lane);
        float2 v1 = *reinterpret_cast<const float2*>(g_bufA + s1 * 64 + 2 * lane);
        float2 v2 = *reinterpret_cast<const float2*>(g_bufA + s2 * 64 + 2 * lane);
        float2 v3 = *reinterpret_cast<const float2*>(g_bufA + s3 * 64 + 2 * lane);
        ax += v0.x + v1.x + v2.x + v3.x;
        ay += v0.y + v1.y + v2.y + v3.y;
    }
    for (; e < end; e++) {
        int s = g_csr[e];
        float2 v = *reinterpret_cast<const float2*>(g_bufA + s * 64 + 2 * lane);
        ax += v.x;
        ay += v.y;
    }

    float di = g_dinv[i];
    float bx = bias[2 * lane];
    float by = bias[2 * lane + 1];
    float2 o;
    o.x = fmaxf(di * ax + bx, 0.f);
    o.y = fmaxf(di * ay + by, 0.f);
    *reinterpret_cast<float2*>(g_bufB + i * 64 + 2 * lane) = o;
}

// -------- fused score + segmented pooling (batch is sorted) --------
__global__ __launch_bounds__(256) void k_pool(const int* __restrict__ bw,
                                              const float* __restrict__ aw,
                                              const float* __restrict__ ab,
                                              const float* __restrict__ mw,
                                              const float* __restrict__ mb) {
    int warp = (blockIdx.x * blockDim.x + threadIdx.x) >> 5;
    int lane = threadIdx.x & 31;
    int n0 = warp * 32;
    if (n0 >= N_NODES) return;
    int n1 = n0 + 32;
    if (n1 > N_NODES) n1 = N_NODES;

    int b64 = g_b64;
    float awx = aw[2 * lane], awy = aw[2 * lane + 1];
    float mwx = mw[2 * lane], mwy = mw[2 * lane + 1];
    float abv = ab[0], mbv = mb[0];

    int cur = -1;
    float accx = 0.f, accy = 0.f;
    for (int n = n0; n < n1; n++) {
        float2 h = *reinterpret_cast<const float2*>(g_bufB + n * 64 + 2 * lane);
        float pa = h.x * awx + h.y * awy;
        float pm = h.x * mwx + h.y * mwy;
#pragma unroll
        for (int o = 16; o > 0; o >>= 1) {
            pa += __shfl_xor_sync(0xffffffffu, pa, o);
            pm += __shfl_xor_sync(0xffffffffu, pm, o);
        }
        float score = (pa + abv) * (1.f / (1.f + expf(-(pm + mbv))));
        int g = b64 ? reinterpret_cast<const int2*>(bw)[n].x : bw[n];
        g = clampi(g, 0, NG - 1);
        if (g != cur) {
            if (cur >= 0) {
                atomicAdd(&g_pooled[cur * 64 + 2 * lane], accx);
                atomicAdd(&g_pooled[cur * 64 + 2 * lane + 1], accy);
            }
            cur = g;
            accx = 0.f;
            accy = 0.f;
        }
        accx += score * h.x;
        accy += score * h.y;
    }
    if (cur >= 0) {
        atomicAdd(&g_pooled[cur * 64 + 2 * lane], accx);
        atomicAdd(&g_pooled[cur * 64 + 2 * lane + 1], accy);
    }
}

// -------- final: out[g] = pooled[g] . out_w + out_b --------
__global__ void k_final(const float* __restrict__ ow, const float* __restrict__ ob,
                        float* __restrict__ out) {
    int warp = (blockIdx.x * blockDim.x + threadIdx.x) >> 5;
    int lane = threadIdx.x & 31;
    if (warp >= NG) return;
    float2 p = *reinterpret_cast<const float2*>(g_pooled + warp * 64 + 2 * lane);
    float wx = ow[2 * lane], wy = ow[2 * lane + 1];
    float s = p.x * wx + p.y * wy;
#pragma unroll
    for (int o = 16; o > 0; o >>= 1) s += __shfl_xor_sync(0xffffffffu, s, o);
    if (lane == 0) out[warp] = s + ob[0];
}

// ---------------------------------------------------------------------------
extern "C" void kernel_launch(void* const* d_in, const int* in_sizes, int n_in,
                              void* d_out, int out_size) {
    const float* x     = (const float*)d_in[0];
    const int*   ew    = (const int*)d_in[1];    // int32 word view of edge_index
    const int*   bw    = (const int*)d_in[2];    // int32 word view of batch
    const float* W1    = (const float*)d_in[3];
    const float* b1    = (const float*)d_in[4];
    const float* W2    = (const float*)d_in[5];
    const float* b2    = (const float*)d_in[6];
    const float* aw    = (const float*)d_in[7];
    const float* ab    = (const float*)d_in[8];
    const float* mw    = (const float*)d_in[9];
    const float* mb    = (const float*)d_in[10];
    const float* ow    = (const float*)d_in[11];
    const float* ob    = (const float*)d_in[12];
    float* out = (float*)d_out;

    k_pre<<<1, 1>>>();
    k_init<<<(NG * HID + 255) / 256, 256>>>(ew, bw);
    k_flag<<<1, 1>>>();
    k_edges<<<(N_EDGES + 255) / 256, 256>>>(ew);
    k_alloc<<<(N_NODES + 255) / 256, 256>>>();
    k_fill<<<(N_EDGES + 255) / 256, 256>>>(ew);

    int gemm_grid = (N_NODES + 127) / 128;
    k_gemm1<<<gemm_grid, 128>>>(x, W1);
    k_agg<<<(N_NODES * 32 + 255) / 256, 256>>>(b1);
    k_gemm2<<<gemm_grid, 128>>>(W2);
    k_agg<<<(N_NODES * 32 + 255) / 256, 256>>>(b2);
    k_pool<<<(N_NODES + 255) / 256, 256>>>(bw, aw, ab, mw, mb);
    k_final<<<(NG * 32 + 255) / 256, 256>>>(ow, ob, out);
}

// round 6
// speedup vs baseline: 1.1698x; 1.0545x over previous
#include <cuda_runtime.h>

#define N_NODES 100000
#define N_EDGES 1000000
#define IN_DIM  128
#define HID     64
#define NG      2048

// ---------------- scratch (static __device__, no allocation) ----------------
__device__ int   g_eor, g_bor;        // detection OR-accumulators (0 => int64)
__device__ int   g_deg[N_NODES];
__device__ float g_dinv[N_NODES];
__device__ int   g_col[N_EDGES];
__device__ int   g_off[N_NODES];
__device__ int   g_cur[N_NODES];
__device__ int   g_csr[N_EDGES];
__device__ int   g_alloc;
__device__ __align__(16) float g_bufA[N_NODES * HID];   // GEMM output (unscaled h)
__device__ __align__(16) float g_bufB[N_NODES * HID];   // aggregated+relu output
__device__ __align__(16) float g_pooled[NG * HID];

__device__ __forceinline__ int clampi(int v, int lo, int hi) {
    return v < lo ? lo : (v > hi ? hi : v);
}

// ---------------- tf32 helpers ----------------
__device__ __forceinline__ unsigned f2tf(float x) {
    unsigned r;
    asm("cvt.rna.tf32.f32 %0, %1;" : "=r"(r) : "f"(x));
    return r;
}

__device__ __forceinline__ void mma_tf32(float* d, const unsigned* a, const unsigned* b) {
    asm volatile(
        "mma.sync.aligned.m16n8k8.row.col.f32.tf32.tf32.f32 "
        "{%0,%1,%2,%3},{%4,%5,%6,%7},{%8,%9},{%0,%1,%2,%3};\n"
        : "+f"(d[0]), "+f"(d[1]), "+f"(d[2]), "+f"(d[3])
        : "r"(a[0]), "r"(a[1]), "r"(a[2]), "r"(a[3]), "r"(b[0]), "r"(b[1]));
}

// ---------------- pre: zero detection accumulators + alloc counter ----------------
__global__ void k_pre() {
    g_eor = 0; g_bor = 0; g_alloc = 0;
}

// ------- init: deg=1 (self loop), pooled=0; also dtype detection ORs -------
__global__ void k_init(const int* __restrict__ ew, const int* __restrict__ bw) {
    int i = blockIdx.x * blockDim.x + threadIdx.x;
    if (i < N_NODES) g_deg[i] = 1;
    if (i < NG * HID) g_pooled[i] = 0.f;
    if (i < 1024) {
        if (ew[2 * i + 1] != 0) atomicOr(&g_eor, 1);
        if (bw[2 * i + 1] != 0) atomicOr(&g_bor, 1);
    }
}

// ---------------- edge pass: count in-degree (dst = edge_index[1]) ----------------
__global__ void k_edges(const int* __restrict__ ew) {
    int e = blockIdx.x * blockDim.x + threadIdx.x;
    if (e >= N_EDGES) return;
    int ei64 = (g_eor == 0);
    int idx = N_EDGES + e;
    int c;
    if (ei64) c = reinterpret_cast<const int2*>(ew)[idx].x;
    else      c = ew[idx];
    c = clampi(c, 0, N_NODES - 1);
    g_col[e] = c;
    atomicAdd(&g_deg[c], 1);
}

// ------- per node: dinv, atomic range allocation (no prefix scan) -------
__global__ void k_alloc() {
    int i = blockIdx.x * blockDim.x + threadIdx.x;
    if (i >= N_NODES) return;
    int d = g_deg[i];
    g_dinv[i] = rsqrtf((float)d);
    int o = atomicAdd(&g_alloc, d - 1);
    g_off[i] = o;
    g_cur[i] = o;
}

// ---------------- fill CSR: slot via per-node cursor ----------------
__global__ void k_fill(const int* __restrict__ ew) {
    int e = blockIdx.x * blockDim.x + threadIdx.x;
    if (e >= N_EDGES) return;
    int ei64 = (g_eor == 0);
    int r;
    if (ei64) r = reinterpret_cast<const int2*>(ew)[e].x;
    else      r = ew[e];
    r = clampi(r, 0, N_NODES - 1);
    int c = g_col[e];
    int s = atomicAdd(&g_cur[c], 1);
    if (s >= 0 && s < N_EDGES) g_csr[s] = r;
}

// ---------------- 3xTF32 MMA GEMM: g_bufA = X @ W  (no scaling) ----------------
// Block: 128 threads (4 warps). Block tile 128 rows x 64 cols. Warp: 32 rows x 64 cols
// = 2 m16 x 8 n8 atoms of m16n8k8. K staged in 32-chunks, operands pre-swizzled
// into fragment order in smem.
template <int KD>
__device__ __forceinline__ void gemm_mma_body(const float* X, const float* __restrict__ W) {
    __shared__ float abuf[4096];   // [k8(4)][m16(8)][lane(32)][reg(4)]
    __shared__ float bbuf[2048];   // [k8(4)][na(8)][lane(32)][reg(2)]

    int tid  = threadIdx.x;
    int lane = tid & 31;
    int warp = tid >> 5;
    int row0 = blockIdx.x * 128;

    float acc[2][8][4];
#pragma unroll
    for (int m = 0; m < 2; m++)
#pragma unroll
        for (int na = 0; na < 8; na++)
#pragma unroll
            for (int q = 0; q < 4; q++) acc[m][na][q] = 0.f;

    for (int ko = 0; ko < KD; ko += 32) {
        __syncthreads();
#pragma unroll
        for (int it = 0; it < 8; it++) {
            int f4 = it * 128 + tid;
            int r  = f4 >> 3;
            int c4 = (f4 & 7) * 4;
            int gr = row0 + r;
            float4 v = make_float4(0.f, 0.f, 0.f, 0.f);
            if (gr < N_NODES)
                v = *reinterpret_cast<const float4*>(X + gr * KD + ko + c4);
            int rr  = r & 15;
            int m16 = r >> 4;
            int k8  = c4 >> 3;
            int kkb = c4 & 7;
            float vv[4] = {v.x, v.y, v.z, v.w};
#pragma unroll
            for (int j = 0; j < 4; j++) {
                int kk  = kkb + j;
                int reg = ((rr >= 8) ? 1 : 0) + ((kk >= 4) ? 2 : 0);
                int t   = (rr & 7) * 4 + (kk & 3);
                abuf[((k8 * 8 + m16) * 32 + t) * 4 + reg] = vv[j];
            }
        }
#pragma unroll
        for (int it = 0; it < 4; it++) {
            int f4 = it * 128 + tid;
            int r  = f4 >> 4;
            int c4 = (f4 & 15) * 4;
            float4 w = *reinterpret_cast<const float4*>(W + (ko + r) * 64 + c4);
            int kk = r & 7;
            int k8 = r >> 3;
            float wv[4] = {w.x, w.y, w.z, w.w};
#pragma unroll
            for (int j = 0; j < 4; j++) {
                int n   = c4 + j;
                int na  = n >> 3;
                int nn  = n & 7;
                int reg = (kk >= 4) ? 1 : 0;
                int t   = nn * 4 + (kk & 3);
                bbuf[((k8 * 8 + na) * 32 + t) * 2 + reg] = wv[j];
            }
        }
        __syncthreads();

#pragma unroll
        for (int k8 = 0; k8 < 4; k8++) {
            unsigned a_hi[2][4], a_lo[2][4];
#pragma unroll
            for (int m = 0; m < 2; m++) {
                float4 ar = *reinterpret_cast<const float4*>(
                    abuf + ((k8 * 8 + warp * 2 + m) * 32 + lane) * 4);
                float av[4] = {ar.x, ar.y, ar.z, ar.w};
#pragma unroll
                for (int q = 0; q < 4; q++) {
                    unsigned h = f2tf(av[q]);
                    a_hi[m][q] = h;
                    a_lo[m][q] = f2tf(av[q] - __uint_as_float(h));
                }
            }
            unsigned b_hi[8][2], b_lo[8][2];
#pragma unroll
            for (int na = 0; na < 8; na++) {
                float2 br = *reinterpret_cast<const float2*>(
                    bbuf + ((k8 * 8 + na) * 32 + lane) * 2);
                float bv[2] = {br.x, br.y};
#pragma unroll
                for (int q = 0; q < 2; q++) {
                    unsigned h = f2tf(bv[q]);
                    b_hi[na][q] = h;
                    b_lo[na][q] = f2tf(bv[q] - __uint_as_float(h));
                }
            }
#pragma unroll
            for (int na = 0; na < 8; na++) {
#pragma unroll
                for (int m = 0; m < 2; m++) {
                    mma_tf32(acc[m][na], a_hi[m], b_hi[na]);
                    mma_tf32(acc[m][na], a_hi[m], b_lo[na]);
                    mma_tf32(acc[m][na], a_lo[m], b_hi[na]);
                }
            }
        }
    }

    // ---- epilogue: store raw h -> g_bufA ----
    int rbase = row0 + warp * 32 + (lane >> 2);
    int cbase = (lane & 3) * 2;
#pragma unroll
    for (int m = 0; m < 2; m++) {
        int r_lo = rbase + m * 16;
        int r_hi = r_lo + 8;
#pragma unroll
        for (int na = 0; na < 8; na++) {
            int c = na * 8 + cbase;
            if (r_lo < N_NODES) {
                float2 v; v.x = acc[m][na][0]; v.y = acc[m][na][1];
                *reinterpret_cast<float2*>(g_bufA + r_lo * 64 + c) = v;
            }
            if (r_hi < N_NODES) {
                float2 v; v.x = acc[m][na][2]; v.y = acc[m][na][3];
                *reinterpret_cast<float2*>(g_bufA + r_hi * 64 + c) = v;
            }
        }
    }
}

__global__ __launch_bounds__(128) void k_gemm1(const float* __restrict__ X,
                                               const float* __restrict__ W) {
    gemm_mma_body<IN_DIM>(X, W);
}

__global__ __launch_bounds__(128) void k_gemm2(const float* __restrict__ W) {
    gemm_mma_body<HID>(g_bufB, W);
}

// -------- pull-aggregate: out = relu(dinv[i]*(dinv[i]*h_i + sum dinv[s]*h_s) + b) --------
__global__ __launch_bounds__(256) void k_agg(const float* __restrict__ bias) {
    int warp = (blockIdx.x * blockDim.x + threadIdx.x) >> 5;
    int lane = threadIdx.x & 31;
    if (warp >= N_NODES) return;
    int i = warp;

    float di = g_dinv[i];
    float2 hs = *reinterpret_cast<const float2*>(g_bufA + i * 64 + 2 * lane);
    float ax = di * hs.x;
    float ay = di * hs.y;

    int beg = g_off[i];
    int end = beg + g_deg[i] - 1;
    if (beg < 0) beg = 0;
    if (end > N_EDGES) end = N_EDGES;
    int e = beg;
    for (; e + 4 <= end; e += 4) {
        int s0 = g_csr[e], s1 = g_csr[e + 1], s2 = g_csr[e + 2], s3 = g_csr[e + 3];
        float w0 = g_dinv[s0], w1 = g_dinv[s1], w2 = g_dinv[s2], w3 = g_dinv[s3];
        float2 v0 = *reinterpret_cast<const float2*>(g_bufA + s0 * 64 + 2 * lane);
        float2 v1 = *reinterpret_cast<const float2*>(g_bufA + s1 * 64 + 2 * lane);
        float2 v2 = *reinterpret_cast<const float2*>(g_bufA + s2 * 64 + 2 * lane);
        float2 v3 = *reinterpret_cast<const float2*>(g_bufA + s3 * 64 + 2 * lane);
        ax += w0 * v0.x + w1 * v1.x + w2 * v2.x + w3 * v3.x;
        ay += w0 * v0.y + w1 * v1.y + w2 * v2.y + w3 * v3.y;
    }
    for (; e < end; e++) {
        int s = g_csr[e];
        float w = g_dinv[s];
        float2 v = *reinterpret_cast<const float2*>(g_bufA + s * 64 + 2 * lane);
        ax += w * v.x;
        ay += w * v.y;
    }

    float bx = bias[2 * lane];
    float by = bias[2 * lane + 1];
    float2 o;
    o.x = fmaxf(di * ax + bx, 0.f);
    o.y = fmaxf(di * ay + by, 0.f);
    *reinterpret_cast<float2*>(g_bufB + i * 64 + 2 * lane) = o;
}

// -------- fused score + segmented pooling (batch is sorted) --------
__global__ __launch_bounds__(256) void k_pool(const int* __restrict__ bw,
                                              const float* __restrict__ aw,
                                              const float* __restrict__ ab,
                                              const float* __restrict__ mw,
                                              const float* __restrict__ mb) {
    int warp = (blockIdx.x * blockDim.x + threadIdx.x) >> 5;
    int lane = threadIdx.x & 31;
    int n0 = warp * 32;
    if (n0 >= N_NODES) return;
    int n1 = n0 + 32;
    if (n1 > N_NODES) n1 = N_NODES;

    int b64 = (g_bor == 0);
    float awx = aw[2 * lane], awy = aw[2 * lane + 1];
    float mwx = mw[2 * lane], mwy = mw[2 * lane + 1];
    float abv = ab[0], mbv = mb[0];

    int cur = -1;
    float accx = 0.f, accy = 0.f;
    for (int n = n0; n < n1; n++) {
        float2 h = *reinterpret_cast<const float2*>(g_bufB + n * 64 + 2 * lane);
        float pa = h.x * awx + h.y * awy;
        float pm = h.x * mwx + h.y * mwy;
#pragma unroll
        for (int o = 16; o > 0; o >>= 1) {
            pa += __shfl_xor_sync(0xffffffffu, pa, o);
            pm += __shfl_xor_sync(0xffffffffu, pm, o);
        }
        float score = (pa + abv) * (1.f / (1.f + expf(-(pm + mbv))));
        int g = b64 ? reinterpret_cast<const int2*>(bw)[n].x : bw[n];
        g = clampi(g, 0, NG - 1);
        if (g != cur) {
            if (cur >= 0) {
                atomicAdd(&g_pooled[cur * 64 + 2 * lane], accx);
                atomicAdd(&g_pooled[cur * 64 + 2 * lane + 1], accy);
            }
            cur = g;
            accx = 0.f;
            accy = 0.f;
        }
        accx += score * h.x;
        accy += score * h.y;
    }
    if (cur >= 0) {
        atomicAdd(&g_pooled[cur * 64 + 2 * lane], accx);
        atomicAdd(&g_pooled[cur * 64 + 2 * lane + 1], accy);
    }
}

// -------- final: out[g] = pooled[g] . out_w + out_b --------
__global__ void k_final(const float* __restrict__ ow, const float* __restrict__ ob,
                        float* __restrict__ out) {
    int warp = (blockIdx.x * blockDim.x + threadIdx.x) >> 5;
    int lane = threadIdx.x & 31;
    if (warp >= NG) return;
    float2 p = *reinterpret_cast<const float2*>(g_pooled + warp * 64 + 2 * lane);
    float wx = ow[2 * lane], wy = ow[2 * lane + 1];
    float s = p.x * wx + p.y * wy;
#pragma unroll
    for (int o = 16; o > 0; o >>= 1) s += __shfl_xor_sync(0xffffffffu, s, o);
    if (lane == 0) out[warp] = s + ob[0];
}

// ---------------------------------------------------------------------------
extern "C" void kernel_launch(void* const* d_in, const int* in_sizes, int n_in,
                              void* d_out, int out_size) {
    const float* x     = (const float*)d_in[0];
    const int*   ew    = (const int*)d_in[1];    // int32 word view of edge_index
    const int*   bw    = (const int*)d_in[2];    // int32 word view of batch
    const float* W1    = (const float*)d_in[3];
    const float* b1    = (const float*)d_in[4];
    const float* W2    = (const float*)d_in[5];
    const float* b2    = (const float*)d_in[6];
    const float* aw    = (const float*)d_in[7];
    const float* ab    = (const float*)d_in[8];
    const float* mw    = (const float*)d_in[9];
    const float* mb    = (const float*)d_in[10];
    const float* ow    = (const float*)d_in[11];
    const float* ob    = (const float*)d_in[12];
    float* out = (float*)d_out;

    int gemm_grid = (N_NODES + 127) / 128;

    // Fork: GEMM1 (depends only on x, W1) runs concurrently with the graph build.
    cudaStream_t s2;
    cudaEvent_t evFork, evJoin;
    cudaStreamCreateWithFlags(&s2, cudaStreamNonBlocking);
    cudaEventCreateWithFlags(&evFork, cudaEventDisableTiming);
    cudaEventCreateWithFlags(&evJoin, cudaEventDisableTiming);

    cudaEventRecord(evFork, 0);
    cudaStreamWaitEvent(s2, evFork, 0);
    k_gemm1<<<gemm_grid, 128, 0, s2>>>(x, W1);
    cudaEventRecord(evJoin, s2);

    // Graph build on the main (capture-origin) stream.
    k_pre<<<1, 1>>>();
    k_init<<<(NG * HID + 255) / 256, 256>>>(ew, bw);
    k_edges<<<(N_EDGES + 255) / 256, 256>>>(ew);
    k_alloc<<<(N_NODES + 255) / 256, 256>>>();
    k_fill<<<(N_EDGES + 255) / 256, 256>>>(ew);

    // Join: aggregation needs both GEMM1 and the CSR.
    cudaStreamWaitEvent(0, evJoin, 0);

    k_agg<<<(N_NODES * 32 + 255) / 256, 256>>>(b1);
    k_gemm2<<<gemm_grid, 128>>>(W2);
    k_agg<<<(N_NODES * 32 + 255) / 256, 256>>>(b2);
    k_pool<<<(N_NODES + 255) / 256, 256>>>(bw, aw, ab, mw, mb);
    k_final<<<(NG * 32 + 255) / 256, 256>>>(ow, ob, out);
}